// round 13
// baseline (speedup 1.0000x reference)
#include <cuda_runtime.h>
#include <cuda_bf16.h>
#include <math.h>

#define B_   32
#define T_   1500
#define E_   512
#define D_   512
#define A_   512
#define H_   4
#define C_   10
#define KK_  201
#define NCH  12
#define TCH  125   // 1500 / 12

#define KTOT 528   // padded K: 512 enc + 10 conv + 6 zero

// ---------------- scratch (static device arrays; no allocation) ----------------
__device__ float g_dec_a[B_ * H_ * A_];          // [B,H,A]
__device__ float g_energy[B_ * H_ * T_];         // [B,H,T]
__device__ float g_aw   [B_ * H_ * T_];          // [B,H,T]
__device__ float g_part [B_ * NCH * H_ * E_];    // [B,chunk,H,E]
__device__ __align__(16) __nv_bfloat16 g_enc_hi[B_ * T_ * E_];   // 49 MB
__device__ __align__(16) __nv_bfloat16 g_enc_lo[B_ * T_ * E_];
__device__ __align__(16) __nv_bfloat16 g_wall_hi[H_ * A_ * KTOT]; // [h][a][k]
__device__ __align__(16) __nv_bfloat16 g_wall_lo[H_ * A_ * KTOT];
__device__ __align__(16) __nv_bfloat16 g_convh[B_ * H_ * T_ * 16]; // conv feats, 16-padded
__device__ __align__(16) __nv_bfloat16 g_convl[B_ * H_ * T_ * 16];

__device__ __forceinline__ float ftanh(float x) {
    float ax = fabsf(x);
    float t  = __expf(-2.0f * ax);
    float r  = __fdividef(1.0f - t, 1.0f + t);
    return copysignf(r, x);
}

// ======================= PTX helpers (base-target only) =======================
__device__ __forceinline__ unsigned smem_u32(const void* p) {
    unsigned a;
    asm("{ .reg .u64 t; cvta.to.shared.u64 t, %1; cvt.u32.u64 %0, t; }" : "=r"(a) : "l"(p));
    return a;
}
__device__ __forceinline__ void cp16(unsigned dst, const void* src, int sz) {
    asm volatile("cp.async.cg.shared.global [%0], [%1], 16, %2;"
                 :: "r"(dst), "l"(__cvta_generic_to_global(src)), "r"(sz));
}
__device__ __forceinline__ void cp_commit() {
    asm volatile("cp.async.commit_group;" ::: "memory");
}
__device__ __forceinline__ void cp_wait1() {
    asm volatile("cp.async.wait_group 1;" ::: "memory");
}
__device__ __forceinline__ void cp_wait0() {
    asm volatile("cp.async.wait_group 0;" ::: "memory");
}
__device__ __forceinline__ void ldsm4(unsigned* r, unsigned addr) {
    asm volatile("ldmatrix.sync.aligned.m8n8.x4.shared.b16 {%0,%1,%2,%3}, [%4];"
                 : "=r"(r[0]), "=r"(r[1]), "=r"(r[2]), "=r"(r[3]) : "r"(addr));
}
// NON-volatile MMA: pure computation, lets ptxas software-pipeline freely.
__device__ __forceinline__ void mma16816(float* c, const unsigned* a, unsigned b0, unsigned b1) {
    asm("mma.sync.aligned.m16n8k16.row.col.f32.bf16.bf16.f32 "
        "{%0,%1,%2,%3}, {%4,%5,%6,%7}, {%8,%9}, {%0,%1,%2,%3};"
        : "+f"(c[0]), "+f"(c[1]), "+f"(c[2]), "+f"(c[3])
        : "r"(a[0]), "r"(a[1]), "r"(a[2]), "r"(a[3]), "r"(b0), "r"(b1));
}

// ---------------- prep: split enc into bf16 hi/lo ----------------
__global__ __launch_bounds__(256) void prep_enc_kernel(const float* __restrict__ enc)
{
    size_t i = ((size_t)blockIdx.x * 256 + threadIdx.x) * 4;
    if (i >= (size_t)B_ * T_ * E_) return;
    float4 x = *(const float4*)(enc + i);
    __nv_bfloat16 h0 = __float2bfloat16(x.x), h1 = __float2bfloat16(x.y),
                  h2 = __float2bfloat16(x.z), h3 = __float2bfloat16(x.w);
    __nv_bfloat16 l0 = __float2bfloat16(x.x - __bfloat162float(h0));
    __nv_bfloat16 l1 = __float2bfloat16(x.y - __bfloat162float(h1));
    __nv_bfloat16 l2 = __float2bfloat16(x.z - __bfloat162float(h2));
    __nv_bfloat16 l3 = __float2bfloat16(x.w - __bfloat162float(h3));
    uint2 hv = make_uint2((unsigned)__bfloat16_as_ushort(h0) | ((unsigned)__bfloat16_as_ushort(h1) << 16),
                          (unsigned)__bfloat16_as_ushort(h2) | ((unsigned)__bfloat16_as_ushort(h3) << 16));
    uint2 lv = make_uint2((unsigned)__bfloat16_as_ushort(l0) | ((unsigned)__bfloat16_as_ushort(l1) << 16),
                          (unsigned)__bfloat16_as_ushort(l2) | ((unsigned)__bfloat16_as_ushort(l3) << 16));
    *(uint2*)(g_enc_hi + i) = hv;
    *(uint2*)(g_enc_lo + i) = lv;
}

// ---------------- prep: w_all[h][a][k] = concat(w_enc^T, w_conv^T, 0) hi/lo ----------------
__global__ __launch_bounds__(256) void prep_w_kernel(
    const float* __restrict__ w_enc, const float* __restrict__ w_conv)
{
    int idx = blockIdx.x * 256 + threadIdx.x;
    if (idx >= H_ * A_ * KTOT) return;
    int k  = idx % KTOT;
    int ha = idx / KTOT;
    int a  = ha % A_;
    int hh = ha / A_;
    float val = 0.f;
    if (k < 512)      val = w_enc[((size_t)hh * 512 + k) * 512 + a];
    else if (k < 522) val = w_conv[((size_t)hh * C_ + (k - 512)) * 512 + a];
    __nv_bfloat16 hi = __float2bfloat16(val);
    float lo = val - __bfloat162float(hi);
    g_wall_hi[idx] = hi;
    g_wall_lo[idx] = __float2bfloat16(lo);
}

// ---------------- dec_a[b,h,a] = sum_d dec_out[b,d] * w_dec[h,d,a] ----------------
__global__ __launch_bounds__(256) void dec_proj_kernel(
    const float* __restrict__ dec_out, const float* __restrict__ w_dec)
{
    int b = blockIdx.x, h = blockIdx.y, tid = threadIdx.x;
    __shared__ float s_dec[D_];
    for (int i = tid; i < D_; i += 256) s_dec[i] = dec_out[b * D_ + i];
    __syncthreads();
    for (int a = tid; a < A_; a += 256) {
        float acc = 0.f;
        const float* w = w_dec + (size_t)(h * D_) * A_ + a;
        #pragma unroll 8
        for (int d = 0; d < D_; d++) acc = fmaf(s_dec[d], w[(size_t)d * A_], acc);
        g_dec_a[(b * H_ + h) * A_ + a] = acc;
    }
}

// ---------------- grouped conv -> bf16 hi/lo features [B,H,T,16] ----------------
// grid (B, H, 4): each z-slice handles 375 t positions for better SM coverage.
__global__ __launch_bounds__(256) void conv_kernel(
    const float* __restrict__ aw_step, const float* __restrict__ conv_k)
{
    int b = blockIdx.x, h = blockIdx.y, zz = blockIdx.z, tid = threadIdx.x;
    __shared__ float s_aw[T_];
    __shared__ float s_k[C_][KK_];
    for (int i = tid; i < T_; i += 256) s_aw[i] = aw_step[(i * H_) + h + (size_t)b * T_ * H_];
    for (int i = tid; i < C_ * KK_; i += 256) s_k[i / KK_][i % KK_] = conv_k[(size_t)(h * C_) * KK_ + i];
    __syncthreads();
    int tbeg = zz * 375, tend = tbeg + 375;
    for (int t = tbeg + tid; t < tend; t += 256) {
        int klo = max(0, 100 - t);
        int khi = min(KK_, T_ + 100 - t);
        float acc[C_];
        #pragma unroll
        for (int c = 0; c < C_; c++) acc[c] = 0.f;
        for (int k = klo; k < khi; k++) {
            float x = s_aw[t + k - 100];
            #pragma unroll
            for (int c = 0; c < C_; c++) acc[c] = fmaf(x, s_k[c][k], acc[c]);
        }
        size_t base = ((size_t)(b * H_ + h) * T_ + t) * 16;
        #pragma unroll
        for (int c = 0; c < 16; c++) {
            float val = (c < C_) ? acc[c] : 0.f;
            __nv_bfloat16 hi = __float2bfloat16(val);
            float lo = val - __bfloat162float(hi);
            g_convh[base + c] = hi;
            g_convl[base + c] = __float2bfloat16(lo);
        }
    }
}

// ======================= fused HMMA energy kernel =======================
// grid (12, H, B), 256 threads (8 warps). CTA: 128 t rows x 512 a (4 tiles of 128).
// K = 528 per a-tile: 8 chunks of 64 (enc) + 1 chunk of 16 (conv).
// Split bf16: D = Ah*Bh + Ah*Bl + Al*Bh (fp32 accum), pass-outermost for ILP.
// Double-buffered cp.async staging overlapped with mma.

#define TSTRIDE 72          // padded smem row stride (bf16 elems) -> 144 B
#define TILE_B  (128 * TSTRIDE * 2)   // 18432 bytes per tile
#define BUF_B   (4 * TILE_B)          // Ah, Al, Bh, Bl = 73728
#define SMEM_E  (2 * BUF_B)           // 147456

__global__ __launch_bounds__(256) void energy_mma_kernel(
    const float* __restrict__ b_enc, const float* __restrict__ v)
{
    extern __shared__ char dynsmem[];
    __shared__ float s_bias[A_];
    __shared__ float s_vv[A_];
    __shared__ float s_e[128];

    int tile = blockIdx.x, h = blockIdx.y, b = blockIdx.z;
    int t0 = tile * 128;
    int tid = threadIdx.x;
    int wid = tid >> 5, lane = tid & 31;
    int wt = wid & 3, wa = wid >> 2;          // warp grid 4(t) x 2(a)

    unsigned sb = smem_u32(dynsmem);

    for (int i = tid; i < A_; i += 256) {
        s_bias[i] = b_enc[h * A_ + i] + g_dec_a[(b * H_ + h) * A_ + i];
        s_vv[i]   = v[h * A_ + i];
    }
    if (tid < 128) s_e[tid] = 0.f;

    auto stage = [&](int g) {
        int at = g / 9, c = g % 9;
        unsigned base = sb + (unsigned)(g & 1) * BUF_B;
        if (c < 8) {
            for (int s = tid; s < 2048; s += 256) {
                int half = s >> 10;
                int r = (s >> 3) & 127;
                int seg = s & 7;
                int t = t0 + r;
                int tc = t < T_ ? t : T_ - 1;
                const __nv_bfloat16* src = (half ? g_enc_lo : g_enc_hi)
                    + ((size_t)(b * T_ + tc) * E_ + c * 64 + seg * 8);
                cp16(base + half * TILE_B + r * 144 + seg * 16, src, (t < T_) ? 16 : 0);
            }
            for (int s = tid; s < 2048; s += 256) {
                int half = s >> 10;
                int r = (s >> 3) & 127;
                int seg = s & 7;
                const __nv_bfloat16* src = (half ? g_wall_lo : g_wall_hi)
                    + ((size_t)(h * A_ + at * 128 + r) * KTOT + c * 64 + seg * 8);
                cp16(base + 2 * TILE_B + half * TILE_B + r * 144 + seg * 16, src, 16);
            }
        } else {
            for (int s = tid; s < 512; s += 256) {
                int half = s >> 8;
                int r = (s >> 1) & 127;
                int seg = s & 1;
                int t = t0 + r;
                int tc = t < T_ ? t : T_ - 1;
                const __nv_bfloat16* src = (half ? g_convl : g_convh)
                    + ((size_t)((b * H_ + h) * T_ + tc) * 16 + seg * 8);
                cp16(base + half * TILE_B + r * 144 + seg * 16, src, (t < T_) ? 16 : 0);
            }
            for (int s = tid; s < 512; s += 256) {
                int half = s >> 8;
                int r = (s >> 1) & 127;
                int seg = s & 1;
                const __nv_bfloat16* src = (half ? g_wall_lo : g_wall_hi)
                    + ((size_t)(h * A_ + at * 128 + r) * KTOT + 512 + seg * 8);
                cp16(base + 2 * TILE_B + half * TILE_B + r * 144 + seg * 16, src, 16);
            }
        }
        cp_commit();
    };

    unsigned aoff0 = (unsigned)((wt * 32 + 0  + (lane & 15)) * 144 + ((lane >> 4) << 4));
    unsigned aoff1 = (unsigned)((wt * 32 + 16 + (lane & 15)) * 144 + ((lane >> 4) << 4));
    unsigned brow = (unsigned)((lane & 7) + ((lane >> 4) << 3));
    unsigned bcol = (unsigned)(((lane >> 3) & 1) << 4);

    float acc[2][8][4];

    stage(0);
    __syncthreads();

    for (int g = 0; g < 36; g++) {
        int at = g / 9, c = g % 9;
        if (g + 1 < 36) stage(g + 1);
        if (g + 1 < 36) cp_wait1(); else cp_wait0();
        __syncthreads();

        if (c == 0) {
            #pragma unroll
            for (int mi = 0; mi < 2; mi++)
                #pragma unroll
                for (int nn = 0; nn < 8; nn++)
                    #pragma unroll
                    for (int q = 0; q < 4; q++) acc[mi][nn][q] = 0.f;
        }

        unsigned base = sb + (unsigned)(g & 1) * BUF_B;
        unsigned sAh = base, sAl = base + TILE_B;
        unsigned sBh = base + 2 * TILE_B, sBl = base + 3 * TILE_B;
        int nks = (c < 8) ? 4 : 1;

        #pragma unroll 1
        for (int ks = 0; ks < nks; ks++) {
            unsigned kb = (unsigned)(ks << 5);
            unsigned ah[2][4], al[2][4], bh[4][4], bl[4][4];
            ldsm4(ah[0], sAh + aoff0 + kb);
            ldsm4(ah[1], sAh + aoff1 + kb);
            ldsm4(al[0], sAl + aoff0 + kb);
            ldsm4(al[1], sAl + aoff1 + kb);
            #pragma unroll
            for (int np = 0; np < 4; np++) {
                unsigned off = (unsigned)((wa * 64 + np * 16 + brow) * 144) + bcol + kb;
                ldsm4(bh[np], sBh + off);
                ldsm4(bl[np], sBl + off);
            }
            // pass 1: Ah * Bh  (16 independent accumulators)
            #pragma unroll
            for (int mi = 0; mi < 2; mi++)
                #pragma unroll
                for (int np = 0; np < 4; np++)
                    #pragma unroll
                    for (int sub = 0; sub < 2; sub++)
                        mma16816(acc[mi][np * 2 + sub], ah[mi], bh[np][sub * 2], bh[np][sub * 2 + 1]);
            // pass 2: Ah * Bl
            #pragma unroll
            for (int mi = 0; mi < 2; mi++)
                #pragma unroll
                for (int np = 0; np < 4; np++)
                    #pragma unroll
                    for (int sub = 0; sub < 2; sub++)
                        mma16816(acc[mi][np * 2 + sub], ah[mi], bl[np][sub * 2], bl[np][sub * 2 + 1]);
            // pass 3: Al * Bh
            #pragma unroll
            for (int mi = 0; mi < 2; mi++)
                #pragma unroll
                for (int np = 0; np < 4; np++)
                    #pragma unroll
                    for (int sub = 0; sub < 2; sub++)
                        mma16816(acc[mi][np * 2 + sub], al[mi], bh[np][sub * 2], bh[np][sub * 2 + 1]);
        }

        if (c == 8) {
            #pragma unroll
            for (int mi = 0; mi < 2; mi++) {
                float e0 = 0.f, e1 = 0.f;
                #pragma unroll
                for (int nn = 0; nn < 8; nn++) {
                    int ng = at * 128 + wa * 64 + nn * 8 + (lane & 3) * 2;
                    float b0v = s_bias[ng], b1v = s_bias[ng + 1];
                    float v0  = s_vv[ng],  v1  = s_vv[ng + 1];
                    e0 = fmaf(ftanh(acc[mi][nn][0] + b0v), v0, e0);
                    e0 = fmaf(ftanh(acc[mi][nn][1] + b1v), v1, e0);
                    e1 = fmaf(ftanh(acc[mi][nn][2] + b0v), v0, e1);
                    e1 = fmaf(ftanh(acc[mi][nn][3] + b1v), v1, e1);
                }
                e0 += __shfl_xor_sync(0xFFFFFFFF, e0, 1);
                e0 += __shfl_xor_sync(0xFFFFFFFF, e0, 2);
                e1 += __shfl_xor_sync(0xFFFFFFFF, e1, 1);
                e1 += __shfl_xor_sync(0xFFFFFFFF, e1, 2);
                if ((lane & 3) == 0) {
                    int r = wt * 32 + mi * 16 + (lane >> 2);
                    atomicAdd(&s_e[r], e0);
                    atomicAdd(&s_e[r + 8], e1);
                }
            }
        }
        __syncthreads();
    }

    if (tid < 128) {
        int t = t0 + tid;
        if (t < T_) g_energy[(b * H_ + h) * T_ + t] = s_e[tid];
    }
}

// ---------------- masked softmax over T per (b,h) ----------------
__global__ __launch_bounds__(256) void softmax_kernel(
    const int* __restrict__ x_lens, float* __restrict__ aw_out)
{
    int b = blockIdx.x, h = blockIdx.y, tid = threadIdx.x;
    __shared__ float s_em[T_];
    __shared__ float s_red[256];
    int len = x_lens[b];
    const float* e = g_energy + (size_t)(b * H_ + h) * T_;

    float mx = -3.4e38f;
    for (int t = tid; t < T_; t += 256) {
        float m = (t < len) ? 1.0f : -1024.0f;
        float val = e[t] * m;
        s_em[t] = val;
        mx = fmaxf(mx, val);
    }
    s_red[tid] = mx; __syncthreads();
    for (int s = 128; s > 0; s >>= 1) { if (tid < s) s_red[tid] = fmaxf(s_red[tid], s_red[tid + s]); __syncthreads(); }
    mx = s_red[0];
    __syncthreads();
    float sum = 0.f;
    for (int t = tid; t < T_; t += 256) { float ex = __expf(s_em[t] - mx); s_em[t] = ex; sum += ex; }
    s_red[tid] = sum; __syncthreads();
    for (int s = 128; s > 0; s >>= 1) { if (tid < s) s_red[tid] += s_red[tid + s]; __syncthreads(); }
    float inv = 1.0f / s_red[0];
    for (int t = tid; t < T_; t += 256) {
        float a = s_em[t] * inv;
        g_aw[(size_t)(b * H_ + h) * T_ + t] = a;
        aw_out[(size_t)(b * T_ + t) * H_ + h] = a;
    }
}

// ---------------- ctx partials ----------------
__global__ __launch_bounds__(256) void ctx_partial_kernel(const float* __restrict__ enc)
{
    int chunk = blockIdx.x, b = blockIdx.y, tid = threadIdx.x;
    int t0 = chunk * TCH;
    __shared__ float s_aw[H_][TCH];
    for (int i = tid; i < H_ * TCH; i += 256) {
        int h = i / TCH, tt = i % TCH;
        s_aw[h][tt] = g_aw[(size_t)(b * H_ + h) * T_ + t0 + tt];
    }
    __syncthreads();
    float acc0[H_] = {}, acc1[H_] = {};
    int e0 = tid, e1 = tid + 256;
    const float* ep = enc + (size_t)(b * T_ + t0) * E_;
    #pragma unroll 4
    for (int tt = 0; tt < TCH; tt++) {
        float f0 = ep[(size_t)tt * E_ + e0];
        float f1 = ep[(size_t)tt * E_ + e1];
        #pragma unroll
        for (int h = 0; h < H_; h++) {
            float a = s_aw[h][tt];
            acc0[h] = fmaf(f0, a, acc0[h]);
            acc1[h] = fmaf(f1, a, acc1[h]);
        }
    }
    float* p = g_part + (size_t)((b * NCH + chunk) * H_) * E_;
    #pragma unroll
    for (int h = 0; h < H_; h++) { p[h * E_ + e0] = acc0[h]; p[h * E_ + e1] = acc1[h]; }
}

// ---------------- reduce partials + MHA projection ----------------
__global__ __launch_bounds__(256) void final_kernel(
    const float* __restrict__ w_mha, const float* __restrict__ b_mha, float* __restrict__ out)
{
    int b = blockIdx.x, tid = threadIdx.x;
    __shared__ float s_ctx[H_ * E_];
    for (int i = tid; i < H_ * E_; i += 256) {
        float s = 0.f;
        #pragma unroll
        for (int ch = 0; ch < NCH; ch++)
            s += g_part[(size_t)((b * NCH + ch) * H_) * E_ + i];
        s_ctx[i] = s;
    }
    __syncthreads();
    int ea = tid, eb = tid + 256;
    float acc_a = b_mha[ea], acc_b = b_mha[eb];
    #pragma unroll 8
    for (int he = 0; he < H_ * E_; he++) {
        float c = s_ctx[he];
        const float* w = w_mha + (size_t)he * E_;
        acc_a = fmaf(c, w[ea], acc_a);
        acc_b = fmaf(c, w[eb], acc_b);
    }
    out[b * E_ + ea] = acc_a;
    out[b * E_ + eb] = acc_b;
}

// ---------------- launch ----------------
extern "C" void kernel_launch(void* const* d_in, const int* in_sizes, int n_in,
                              void* d_out, int out_size)
{
    const float* enc     = (const float*)d_in[0];
    const int*   x_lens  = (const int*)  d_in[1];
    const float* dec_out = (const float*)d_in[2];
    const float* aw_step = (const float*)d_in[3];
    const float* w_enc   = (const float*)d_in[4];
    const float* b_enc   = (const float*)d_in[5];
    const float* w_dec   = (const float*)d_in[6];
    const float* w_conv  = (const float*)d_in[7];
    const float* conv_k  = (const float*)d_in[8];
    const float* v       = (const float*)d_in[9];
    const float* w_mha   = (const float*)d_in[10];
    const float* b_mha   = (const float*)d_in[11];

    float* out     = (float*)d_out;
    float* ctx_out = out;              // B*E floats
    float* aw_out  = out + B_ * E_;    // B*T*H floats

    cudaFuncSetAttribute(energy_mma_kernel, cudaFuncAttributeMaxDynamicSharedMemorySize, SMEM_E);

    prep_enc_kernel<<<(B_ * T_ * E_ / 4 + 255) / 256, 256>>>(enc);
    prep_w_kernel<<<(H_ * A_ * KTOT + 255) / 256, 256>>>(w_enc, w_conv);
    dec_proj_kernel<<<dim3(B_, H_), 256>>>(dec_out, w_dec);
    conv_kernel<<<dim3(B_, H_, 4), 256>>>(aw_step, conv_k);
    energy_mma_kernel<<<dim3(NCH, H_, B_), 256, SMEM_E>>>(b_enc, v);
    softmax_kernel<<<dim3(B_, H_), 256>>>(x_lens, aw_out);
    ctx_partial_kernel<<<dim3(NCH, B_), 256>>>(enc);
    final_kernel<<<B_, 256>>>(w_mha, b_mha, ctx_out);
}

// round 14
// speedup vs baseline: 1.4636x; 1.4636x over previous
#include <cuda_runtime.h>
#include <cuda_fp16.h>
#include <math.h>

#define B_   32
#define T_   1500
#define E_   512
#define D_   512
#define A_   512
#define H_   4
#define C_   10
#define KK_  201
#define NCH  12
#define TCH  125   // 1500 / 12

#define KTOT 528   // padded K: 512 enc + 10 conv + 6 zero

// ---------------- scratch (static device arrays; no allocation) ----------------
__device__ float g_dec_a[B_ * H_ * A_];          // [B,H,A]
__device__ float g_energy[B_ * H_ * T_];         // [B,H,T]
__device__ float g_aw   [B_ * H_ * T_];          // [B,H,T]
__device__ float g_part [B_ * NCH * H_ * E_];    // [B,chunk,H,E]
__device__ __align__(16) __half g_enc_hi[B_ * T_ * E_];   // fp16 hi of enc
__device__ __align__(16) __half g_enc_lo[B_ * T_ * E_];   // fp16 residual
__device__ __align__(16) __half g_wall[H_ * A_ * KTOT];   // [h][a][k] fp16 weights (single)
__device__ __align__(16) __half g_convh[B_ * H_ * T_ * 16]; // conv feats hi, 16-padded
__device__ __align__(16) __half g_convl[B_ * H_ * T_ * 16]; // conv feats residual

__device__ __forceinline__ float ftanh(float x) {
    float ax = fabsf(x);
    float t  = __expf(-2.0f * ax);
    float r  = __fdividef(1.0f - t, 1.0f + t);
    return copysignf(r, x);
}

// ======================= PTX helpers (base-target only) =======================
__device__ __forceinline__ unsigned smem_u32(const void* p) {
    unsigned a;
    asm("{ .reg .u64 t; cvta.to.shared.u64 t, %1; cvt.u32.u64 %0, t; }" : "=r"(a) : "l"(p));
    return a;
}
__device__ __forceinline__ void cp16(unsigned dst, const void* src, int sz) {
    asm volatile("cp.async.cg.shared.global [%0], [%1], 16, %2;"
                 :: "r"(dst), "l"(__cvta_generic_to_global(src)), "r"(sz));
}
__device__ __forceinline__ void cp_commit() {
    asm volatile("cp.async.commit_group;" ::: "memory");
}
__device__ __forceinline__ void cp_wait1() {
    asm volatile("cp.async.wait_group 1;" ::: "memory");
}
__device__ __forceinline__ void cp_wait0() {
    asm volatile("cp.async.wait_group 0;" ::: "memory");
}
__device__ __forceinline__ void ldsm4(unsigned* r, unsigned addr) {
    asm volatile("ldmatrix.sync.aligned.m8n8.x4.shared.b16 {%0,%1,%2,%3}, [%4];"
                 : "=r"(r[0]), "=r"(r[1]), "=r"(r[2]), "=r"(r[3]) : "r"(addr));
}
__device__ __forceinline__ void mma16816(float* c, const unsigned* a, unsigned b0, unsigned b1) {
    asm("mma.sync.aligned.m16n8k16.row.col.f32.f16.f16.f32 "
        "{%0,%1,%2,%3}, {%4,%5,%6,%7}, {%8,%9}, {%0,%1,%2,%3};"
        : "+f"(c[0]), "+f"(c[1]), "+f"(c[2]), "+f"(c[3])
        : "r"(a[0]), "r"(a[1]), "r"(a[2]), "r"(a[3]), "r"(b0), "r"(b1));
}

// ---------------- prep: split enc into fp16 hi + residual ----------------
__global__ __launch_bounds__(256) void prep_enc_kernel(const float* __restrict__ enc)
{
    size_t i = ((size_t)blockIdx.x * 256 + threadIdx.x) * 4;
    if (i >= (size_t)B_ * T_ * E_) return;
    float4 x = *(const float4*)(enc + i);
    __half h0 = __float2half_rn(x.x), h1 = __float2half_rn(x.y),
           h2 = __float2half_rn(x.z), h3 = __float2half_rn(x.w);
    __half l0 = __float2half_rn(x.x - __half2float(h0));
    __half l1 = __float2half_rn(x.y - __half2float(h1));
    __half l2 = __float2half_rn(x.z - __half2float(h2));
    __half l3 = __float2half_rn(x.w - __half2float(h3));
    uint2 hv = make_uint2((unsigned)__half_as_ushort(h0) | ((unsigned)__half_as_ushort(h1) << 16),
                          (unsigned)__half_as_ushort(h2) | ((unsigned)__half_as_ushort(h3) << 16));
    uint2 lv = make_uint2((unsigned)__half_as_ushort(l0) | ((unsigned)__half_as_ushort(l1) << 16),
                          (unsigned)__half_as_ushort(l2) | ((unsigned)__half_as_ushort(l3) << 16));
    *(uint2*)(g_enc_hi + i) = hv;
    *(uint2*)(g_enc_lo + i) = lv;
}

// ---------------- prep: w_all[h][a][k] = concat(w_enc^T, w_conv^T, 0) fp16 ----------------
__global__ __launch_bounds__(256) void prep_w_kernel(
    const float* __restrict__ w_enc, const float* __restrict__ w_conv)
{
    int idx = blockIdx.x * 256 + threadIdx.x;
    if (idx >= H_ * A_ * KTOT) return;
    int k  = idx % KTOT;
    int ha = idx / KTOT;
    int a  = ha % A_;
    int hh = ha / A_;
    float val = 0.f;
    if (k < 512)      val = w_enc[((size_t)hh * 512 + k) * 512 + a];
    else if (k < 522) val = w_conv[((size_t)hh * C_ + (k - 512)) * 512 + a];
    g_wall[idx] = __float2half_rn(val);
}

// ---------------- dec_a[b,h,a] = sum_d dec_out[b,d] * w_dec[h,d,a] ----------------
__global__ __launch_bounds__(256) void dec_proj_kernel(
    const float* __restrict__ dec_out, const float* __restrict__ w_dec)
{
    int b = blockIdx.x, h = blockIdx.y, tid = threadIdx.x;
    __shared__ float s_dec[D_];
    for (int i = tid; i < D_; i += 256) s_dec[i] = dec_out[b * D_ + i];
    __syncthreads();
    for (int a = tid; a < A_; a += 256) {
        float acc = 0.f;
        const float* w = w_dec + (size_t)(h * D_) * A_ + a;
        #pragma unroll 8
        for (int d = 0; d < D_; d++) acc = fmaf(s_dec[d], w[(size_t)d * A_], acc);
        g_dec_a[(b * H_ + h) * A_ + a] = acc;
    }
}

// ---------------- grouped conv -> fp16 hi/lo features [B,H,T,16] ----------------
__global__ __launch_bounds__(256) void conv_kernel(
    const float* __restrict__ aw_step, const float* __restrict__ conv_k)
{
    int b = blockIdx.x, h = blockIdx.y, zz = blockIdx.z, tid = threadIdx.x;
    __shared__ float s_aw[T_];
    __shared__ float s_k[C_][KK_];
    for (int i = tid; i < T_; i += 256) s_aw[i] = aw_step[(i * H_) + h + (size_t)b * T_ * H_];
    for (int i = tid; i < C_ * KK_; i += 256) s_k[i / KK_][i % KK_] = conv_k[(size_t)(h * C_) * KK_ + i];
    __syncthreads();
    int tbeg = zz * 375, tend = tbeg + 375;
    for (int t = tbeg + tid; t < tend; t += 256) {
        int klo = max(0, 100 - t);
        int khi = min(KK_, T_ + 100 - t);
        float acc[C_];
        #pragma unroll
        for (int c = 0; c < C_; c++) acc[c] = 0.f;
        for (int k = klo; k < khi; k++) {
            float x = s_aw[t + k - 100];
            #pragma unroll
            for (int c = 0; c < C_; c++) acc[c] = fmaf(x, s_k[c][k], acc[c]);
        }
        size_t base = ((size_t)(b * H_ + h) * T_ + t) * 16;
        #pragma unroll
        for (int c = 0; c < 16; c++) {
            float val = (c < C_) ? acc[c] : 0.f;
            __half hi = __float2half_rn(val);
            g_convh[base + c] = hi;
            g_convl[base + c] = __float2half_rn(val - __half2float(hi));
        }
    }
}

// ======================= fused HMMA energy kernel =======================
// grid (12, H, B), 256 threads (8 warps), 2 CTAs/SM target. CTA: 128t x 512a.
// K = 528: 8 chunks of 64 (enc) + 1 chunk of 16 (conv).
// fp16 2-pass: D = Ah*B + Al*B (fp32 accum). Double-buffered cp.async.
// All smem dynamic so 2 CTAs fit: 2*BUF + bias/vv/e tail.

#define TSTRIDE_B 144                 // bytes per smem row (72 halves), 16B-aligned, conflict-free
#define TILE_B  (128 * TSTRIDE_B)     // 18432 bytes per tile
#define BUF_B   (3 * TILE_B)          // Ah, Al, B = 55296
#define SM_BIAS (2 * BUF_B)           // 110592
#define SM_VV   (SM_BIAS + 2048)
#define SM_SE   (SM_VV + 2048)
#define SMEM_E  (SM_SE + 512)         // 115200

__global__ __launch_bounds__(256, 2) void energy_mma_kernel(
    const float* __restrict__ b_enc, const float* __restrict__ v)
{
    extern __shared__ char dynsmem[];
    float* s_bias = (float*)(dynsmem + SM_BIAS);
    float* s_vv   = (float*)(dynsmem + SM_VV);
    float* s_e    = (float*)(dynsmem + SM_SE);

    int tile = blockIdx.x, h = blockIdx.y, b = blockIdx.z;
    int t0 = tile * 128;
    int tid = threadIdx.x;
    int wid = tid >> 5, lane = tid & 31;
    int wt = wid & 3, wa = wid >> 2;          // warp grid 4(t) x 2(a)

    unsigned sb = smem_u32(dynsmem);

    for (int i = tid; i < A_; i += 256) {
        s_bias[i] = b_enc[h * A_ + i] + g_dec_a[(b * H_ + h) * A_ + i];
        s_vv[i]   = v[h * A_ + i];
    }
    if (tid < 128) s_e[tid] = 0.f;

    auto stage = [&](int g) {
        int at = g / 9, c = g % 9;
        unsigned base = sb + (unsigned)(g & 1) * BUF_B;
        if (c < 8) {
            // A: enc hi/lo [128 rows][64 k]
            for (int s = tid; s < 2048; s += 256) {
                int half = s >> 10;
                int r = (s >> 3) & 127;
                int seg = s & 7;
                int t = t0 + r;
                int tc = t < T_ ? t : T_ - 1;
                const __half* src = (half ? g_enc_lo : g_enc_hi)
                    + ((size_t)(b * T_ + tc) * E_ + c * 64 + seg * 8);
                cp16(base + half * TILE_B + r * TSTRIDE_B + seg * 16, src, (t < T_) ? 16 : 0);
            }
            // B: w_all single fp16 [128 a rows][64 k]
            for (int s = tid; s < 1024; s += 256) {
                int r = (s >> 3) & 127;
                int seg = s & 7;
                const __half* src = g_wall
                    + ((size_t)(h * A_ + at * 128 + r) * KTOT + c * 64 + seg * 8);
                cp16(base + 2 * TILE_B + r * TSTRIDE_B + seg * 16, src, 16);
            }
        } else {
            for (int s = tid; s < 512; s += 256) {
                int half = s >> 8;
                int r = (s >> 1) & 127;
                int seg = s & 1;
                int t = t0 + r;
                int tc = t < T_ ? t : T_ - 1;
                const __half* src = (half ? g_convl : g_convh)
                    + ((size_t)((b * H_ + h) * T_ + tc) * 16 + seg * 8);
                cp16(base + half * TILE_B + r * TSTRIDE_B + seg * 16, src, (t < T_) ? 16 : 0);
            }
            for (int s = tid; s < 256; s += 256) {
                int r = s >> 1;
                int seg = s & 1;
                const __half* src = g_wall
                    + ((size_t)(h * A_ + at * 128 + r) * KTOT + 512 + seg * 8);
                cp16(base + 2 * TILE_B + r * TSTRIDE_B + seg * 16, src, 16);
            }
            // second half of B conv rows (256 ops total needed: 128 rows x 2 segs)
            for (int s = tid + 256; s < 256; s += 256) {} // (covered above: 256 ops == blockDim)
        }
        cp_commit();
    };

    unsigned aoff0 = (unsigned)((wt * 32 + 0  + (lane & 15)) * TSTRIDE_B + ((lane >> 4) << 4));
    unsigned aoff1 = (unsigned)((wt * 32 + 16 + (lane & 15)) * TSTRIDE_B + ((lane >> 4) << 4));
    unsigned brow = (unsigned)((lane & 7) + ((lane >> 4) << 3));
    unsigned bcol = (unsigned)(((lane >> 3) & 1) << 4);

    float acc[2][8][4];

    stage(0);
    __syncthreads();

    for (int g = 0; g < 36; g++) {
        int at = g / 9, c = g % 9;
        if (g + 1 < 36) stage(g + 1);
        if (g + 1 < 36) cp_wait1(); else cp_wait0();
        __syncthreads();

        if (c == 0) {
            #pragma unroll
            for (int mi = 0; mi < 2; mi++)
                #pragma unroll
                for (int nn = 0; nn < 8; nn++)
                    #pragma unroll
                    for (int q = 0; q < 4; q++) acc[mi][nn][q] = 0.f;
        }

        unsigned base = sb + (unsigned)(g & 1) * BUF_B;
        unsigned sAh = base, sAl = base + TILE_B, sB = base + 2 * TILE_B;
        int nks = (c < 8) ? 4 : 1;

        #pragma unroll 1
        for (int ks = 0; ks < nks; ks++) {
            unsigned kb = (unsigned)(ks << 5);
            unsigned ah[2][4], al[2][4], bb[4][4];
            ldsm4(ah[0], sAh + aoff0 + kb);
            ldsm4(ah[1], sAh + aoff1 + kb);
            ldsm4(al[0], sAl + aoff0 + kb);
            ldsm4(al[1], sAl + aoff1 + kb);
            #pragma unroll
            for (int np = 0; np < 4; np++) {
                unsigned off = (unsigned)((wa * 64 + np * 16 + brow) * TSTRIDE_B) + bcol + kb;
                ldsm4(bb[np], sB + off);
            }
            // pass 1: Ah * B
            #pragma unroll
            for (int mi = 0; mi < 2; mi++)
                #pragma unroll
                for (int np = 0; np < 4; np++)
                    #pragma unroll
                    for (int sub = 0; sub < 2; sub++)
                        mma16816(acc[mi][np * 2 + sub], ah[mi], bb[np][sub * 2], bb[np][sub * 2 + 1]);
            // pass 2: Al * B
            #pragma unroll
            for (int mi = 0; mi < 2; mi++)
                #pragma unroll
                for (int np = 0; np < 4; np++)
                    #pragma unroll
                    for (int sub = 0; sub < 2; sub++)
                        mma16816(acc[mi][np * 2 + sub], al[mi], bb[np][sub * 2], bb[np][sub * 2 + 1]);
        }

        if (c == 8) {
            #pragma unroll
            for (int mi = 0; mi < 2; mi++) {
                float e0 = 0.f, e1 = 0.f;
                #pragma unroll
                for (int nn = 0; nn < 8; nn++) {
                    int ng = at * 128 + wa * 64 + nn * 8 + (lane & 3) * 2;
                    float b0v = s_bias[ng], b1v = s_bias[ng + 1];
                    float v0  = s_vv[ng],  v1  = s_vv[ng + 1];
                    e0 = fmaf(ftanh(acc[mi][nn][0] + b0v), v0, e0);
                    e0 = fmaf(ftanh(acc[mi][nn][1] + b1v), v1, e0);
                    e1 = fmaf(ftanh(acc[mi][nn][2] + b0v), v0, e1);
                    e1 = fmaf(ftanh(acc[mi][nn][3] + b1v), v1, e1);
                }
                e0 += __shfl_xor_sync(0xFFFFFFFF, e0, 1);
                e0 += __shfl_xor_sync(0xFFFFFFFF, e0, 2);
                e1 += __shfl_xor_sync(0xFFFFFFFF, e1, 1);
                e1 += __shfl_xor_sync(0xFFFFFFFF, e1, 2);
                if ((lane & 3) == 0) {
                    int r = wt * 32 + mi * 16 + (lane >> 2);
                    atomicAdd(&s_e[r], e0);
                    atomicAdd(&s_e[r + 8], e1);
                }
            }
        }
        __syncthreads();
    }

    if (tid < 128) {
        int t = t0 + tid;
        if (t < T_) g_energy[(b * H_ + h) * T_ + t] = s_e[tid];
    }
}

// ---------------- masked softmax over T per (b,h) ----------------
__global__ __launch_bounds__(256) void softmax_kernel(
    const int* __restrict__ x_lens, float* __restrict__ aw_out)
{
    int b = blockIdx.x, h = blockIdx.y, tid = threadIdx.x;
    __shared__ float s_em[T_];
    __shared__ float s_red[256];
    int len = x_lens[b];
    const float* e = g_energy + (size_t)(b * H_ + h) * T_;

    float mx = -3.4e38f;
    for (int t = tid; t < T_; t += 256) {
        float m = (t < len) ? 1.0f : -1024.0f;
        float val = e[t] * m;
        s_em[t] = val;
        mx = fmaxf(mx, val);
    }
    s_red[tid] = mx; __syncthreads();
    for (int s = 128; s > 0; s >>= 1) { if (tid < s) s_red[tid] = fmaxf(s_red[tid], s_red[tid + s]); __syncthreads(); }
    mx = s_red[0];
    __syncthreads();
    float sum = 0.f;
    for (int t = tid; t < T_; t += 256) { float ex = __expf(s_em[t] - mx); s_em[t] = ex; sum += ex; }
    s_red[tid] = sum; __syncthreads();
    for (int s = 128; s > 0; s >>= 1) { if (tid < s) s_red[tid] += s_red[tid + s]; __syncthreads(); }
    float inv = 1.0f / s_red[0];
    for (int t = tid; t < T_; t += 256) {
        float a = s_em[t] * inv;
        g_aw[(size_t)(b * H_ + h) * T_ + t] = a;
        aw_out[(size_t)(b * T_ + t) * H_ + h] = a;
    }
}

// ---------------- ctx partials ----------------
__global__ __launch_bounds__(256) void ctx_partial_kernel(const float* __restrict__ enc)
{
    int chunk = blockIdx.x, b = blockIdx.y, tid = threadIdx.x;
    int t0 = chunk * TCH;
    __shared__ float s_aw[H_][TCH];
    for (int i = tid; i < H_ * TCH; i += 256) {
        int h = i / TCH, tt = i % TCH;
        s_aw[h][tt] = g_aw[(size_t)(b * H_ + h) * T_ + t0 + tt];
    }
    __syncthreads();
    float acc0[H_] = {}, acc1[H_] = {};
    int e0 = tid, e1 = tid + 256;
    const float* ep = enc + (size_t)(b * T_ + t0) * E_;
    #pragma unroll 4
    for (int tt = 0; tt < TCH; tt++) {
        float f0 = ep[(size_t)tt * E_ + e0];
        float f1 = ep[(size_t)tt * E_ + e1];
        #pragma unroll
        for (int h = 0; h < H_; h++) {
            float a = s_aw[h][tt];
            acc0[h] = fmaf(f0, a, acc0[h]);
            acc1[h] = fmaf(f1, a, acc1[h]);
        }
    }
    float* p = g_part + (size_t)((b * NCH + chunk) * H_) * E_;
    #pragma unroll
    for (int h = 0; h < H_; h++) { p[h * E_ + e0] = acc0[h]; p[h * E_ + e1] = acc1[h]; }
}

// ---------------- reduce partials + MHA projection ----------------
__global__ __launch_bounds__(256) void final_kernel(
    const float* __restrict__ w_mha, const float* __restrict__ b_mha, float* __restrict__ out)
{
    int b = blockIdx.x, tid = threadIdx.x;
    __shared__ float s_ctx[H_ * E_];
    for (int i = tid; i < H_ * E_; i += 256) {
        float s = 0.f;
        #pragma unroll
        for (int ch = 0; ch < NCH; ch++)
            s += g_part[(size_t)((b * NCH + ch) * H_) * E_ + i];
        s_ctx[i] = s;
    }
    __syncthreads();
    int ea = tid, eb = tid + 256;
    float acc_a = b_mha[ea], acc_b = b_mha[eb];
    #pragma unroll 8
    for (int he = 0; he < H_ * E_; he++) {
        float c = s_ctx[he];
        const float* w = w_mha + (size_t)he * E_;
        acc_a = fmaf(c, w[ea], acc_a);
        acc_b = fmaf(c, w[eb], acc_b);
    }
    out[b * E_ + ea] = acc_a;
    out[b * E_ + eb] = acc_b;
}

// ---------------- launch ----------------
extern "C" void kernel_launch(void* const* d_in, const int* in_sizes, int n_in,
                              void* d_out, int out_size)
{
    const float* enc     = (const float*)d_in[0];
    const int*   x_lens  = (const int*)  d_in[1];
    const float* dec_out = (const float*)d_in[2];
    const float* aw_step = (const float*)d_in[3];
    const float* w_enc   = (const float*)d_in[4];
    const float* b_enc   = (const float*)d_in[5];
    const float* w_dec   = (const float*)d_in[6];
    const float* w_conv  = (const float*)d_in[7];
    const float* conv_k  = (const float*)d_in[8];
    const float* v       = (const float*)d_in[9];
    const float* w_mha   = (const float*)d_in[10];
    const float* b_mha   = (const float*)d_in[11];

    float* out     = (float*)d_out;
    float* ctx_out = out;              // B*E floats
    float* aw_out  = out + B_ * E_;    // B*T*H floats

    cudaFuncSetAttribute(energy_mma_kernel, cudaFuncAttributeMaxDynamicSharedMemorySize, SMEM_E);

    prep_enc_kernel<<<(B_ * T_ * E_ / 4 + 255) / 256, 256>>>(enc);
    prep_w_kernel<<<(H_ * A_ * KTOT + 255) / 256, 256>>>(w_enc, w_conv);
    dec_proj_kernel<<<dim3(B_, H_), 256>>>(dec_out, w_dec);
    conv_kernel<<<dim3(B_, H_, 4), 256>>>(aw_step, conv_k);
    energy_mma_kernel<<<dim3(NCH, H_, B_), 256, SMEM_E>>>(b_enc, v);
    softmax_kernel<<<dim3(B_, H_), 256>>>(x_lens, aw_out);
    ctx_partial_kernel<<<dim3(NCH, B_), 256>>>(enc);
    final_kernel<<<B_, 256>>>(w_mha, b_mha, ctx_out);
}

// round 15
// speedup vs baseline: 2.1070x; 1.4396x over previous
#include <cuda_runtime.h>
#include <cuda_fp16.h>
#include <math.h>

#define B_   32
#define T_   1500
#define E_   512
#define D_   512
#define A_   512
#define H_   4
#define C_   10
#define KK_  201
#define NCH  12
#define TCH  125   // 1500 / 12

#define KTOT 528   // padded K: 512 enc + 10 conv + 6 zero

// ---------------- scratch (static device arrays; no allocation) ----------------
__device__ float g_dec_a[B_ * H_ * A_];          // [B,H,A]
__device__ float g_energy[B_ * H_ * T_];         // [B,H,T]
__device__ float g_aw   [B_ * H_ * T_];          // [B,H,T]
__device__ float g_part [B_ * NCH * H_ * E_];    // [B,chunk,H,E]
__device__ __align__(16) __half g_enc_h[B_ * T_ * E_];    // fp16 enc
__device__ __align__(16) __half g_wall[H_ * A_ * KTOT];   // [h][a][k] fp16 weights
__device__ __align__(16) __half g_convh[B_ * H_ * T_ * 16]; // conv feats, 16-padded

__device__ __forceinline__ float ftanh(float x) {
    float ax = fabsf(x);
    float t  = __expf(-2.0f * ax);
    float r  = __fdividef(1.0f - t, 1.0f + t);
    return copysignf(r, x);
}

// ======================= PTX helpers (base-target only) =======================
__device__ __forceinline__ unsigned smem_u32(const void* p) {
    unsigned a;
    asm("{ .reg .u64 t; cvta.to.shared.u64 t, %1; cvt.u32.u64 %0, t; }" : "=r"(a) : "l"(p));
    return a;
}
__device__ __forceinline__ void cp16(unsigned dst, const void* src, int sz) {
    asm volatile("cp.async.cg.shared.global [%0], [%1], 16, %2;"
                 :: "r"(dst), "l"(__cvta_generic_to_global(src)), "r"(sz));
}
__device__ __forceinline__ void cp_commit() {
    asm volatile("cp.async.commit_group;" ::: "memory");
}
__device__ __forceinline__ void cp_wait1() {
    asm volatile("cp.async.wait_group 1;" ::: "memory");
}
__device__ __forceinline__ void cp_wait0() {
    asm volatile("cp.async.wait_group 0;" ::: "memory");
}
__device__ __forceinline__ void ldsm4(unsigned* r, unsigned addr) {
    asm volatile("ldmatrix.sync.aligned.m8n8.x4.shared.b16 {%0,%1,%2,%3}, [%4];"
                 : "=r"(r[0]), "=r"(r[1]), "=r"(r[2]), "=r"(r[3]) : "r"(addr));
}
__device__ __forceinline__ void mma16816(float* c, const unsigned* a, unsigned b0, unsigned b1) {
    asm("mma.sync.aligned.m16n8k16.row.col.f32.f16.f16.f32 "
        "{%0,%1,%2,%3}, {%4,%5,%6,%7}, {%8,%9}, {%0,%1,%2,%3};"
        : "+f"(c[0]), "+f"(c[1]), "+f"(c[2]), "+f"(c[3])
        : "r"(a[0]), "r"(a[1]), "r"(a[2]), "r"(a[3]), "r"(b0), "r"(b1));
}

// ---------------- prep: enc -> fp16 ----------------
__global__ __launch_bounds__(256) void prep_enc_kernel(const float* __restrict__ enc)
{
    size_t i = ((size_t)blockIdx.x * 256 + threadIdx.x) * 4;
    if (i >= (size_t)B_ * T_ * E_) return;
    float4 x = *(const float4*)(enc + i);
    __half h0 = __float2half_rn(x.x), h1 = __float2half_rn(x.y),
           h2 = __float2half_rn(x.z), h3 = __float2half_rn(x.w);
    uint2 hv = make_uint2((unsigned)__half_as_ushort(h0) | ((unsigned)__half_as_ushort(h1) << 16),
                          (unsigned)__half_as_ushort(h2) | ((unsigned)__half_as_ushort(h3) << 16));
    *(uint2*)(g_enc_h + i) = hv;
}

// ---------------- prep: w_all[h][a][k] = concat(w_enc^T, w_conv^T, 0) fp16 ----------------
__global__ __launch_bounds__(256) void prep_w_kernel(
    const float* __restrict__ w_enc, const float* __restrict__ w_conv)
{
    int idx = blockIdx.x * 256 + threadIdx.x;
    if (idx >= H_ * A_ * KTOT) return;
    int k  = idx % KTOT;
    int ha = idx / KTOT;
    int a  = ha % A_;
    int hh = ha / A_;
    float val = 0.f;
    if (k < 512)      val = w_enc[((size_t)hh * 512 + k) * 512 + a];
    else if (k < 522) val = w_conv[((size_t)hh * C_ + (k - 512)) * 512 + a];
    g_wall[idx] = __float2half_rn(val);
}

// ---------------- dec_a[b,h,a] = sum_d dec_out[b,d] * w_dec[h,d,a] ----------------
__global__ __launch_bounds__(256) void dec_proj_kernel(
    const float* __restrict__ dec_out, const float* __restrict__ w_dec)
{
    int b = blockIdx.x, h = blockIdx.y, tid = threadIdx.x;
    __shared__ float s_dec[D_];
    for (int i = tid; i < D_; i += 256) s_dec[i] = dec_out[b * D_ + i];
    __syncthreads();
    for (int a = tid; a < A_; a += 256) {
        float acc = 0.f;
        const float* w = w_dec + (size_t)(h * D_) * A_ + a;
        #pragma unroll 8
        for (int d = 0; d < D_; d++) acc = fmaf(s_dec[d], w[(size_t)d * A_], acc);
        g_dec_a[(b * H_ + h) * A_ + a] = acc;
    }
}

// ---------------- grouped conv -> fp16 features [B,H,T,16] ----------------
// Zero-padded aw (no edge branches), kernels transposed for float4 LDS,
// 6 t-values per thread (LDS:FMA = 9:60).
#define TPAD 1700   // 100 + 1500 + 100
__global__ __launch_bounds__(256) void conv_kernel(
    const float* __restrict__ aw_step, const float* __restrict__ conv_k)
{
    int b = blockIdx.x, h = blockIdx.y, tid = threadIdx.x;
    __shared__ float s_awp[TPAD];
    __shared__ __align__(16) float s_kt[KK_][12];   // [k][c], 12-padded (48B rows)
    for (int i = tid; i < TPAD; i += 256) {
        int t = i - 100;
        s_awp[i] = (t >= 0 && t < T_) ? aw_step[(size_t)b * T_ * H_ + t * H_ + h] : 0.f;
    }
    for (int i = tid; i < KK_ * 12; i += 256) {
        int k = i / 12, c = i % 12;
        s_kt[k][c] = (c < C_) ? conv_k[(size_t)(h * C_ + c) * KK_ + k] : 0.f;
    }
    __syncthreads();

    float acc[6][C_];
    #pragma unroll
    for (int j = 0; j < 6; j++)
        #pragma unroll
        for (int c = 0; c < C_; c++) acc[j][c] = 0.f;

    for (int k = 0; k < KK_; k++) {
        float4 k0 = *(const float4*)&s_kt[k][0];
        float4 k1 = *(const float4*)&s_kt[k][4];
        float2 k2 = *(const float2*)&s_kt[k][8];
        #pragma unroll
        for (int j = 0; j < 6; j++) {
            int t = tid + j * 256;
            float x = (t < T_) ? s_awp[t + k] : 0.f;
            acc[j][0] = fmaf(x, k0.x, acc[j][0]); acc[j][1] = fmaf(x, k0.y, acc[j][1]);
            acc[j][2] = fmaf(x, k0.z, acc[j][2]); acc[j][3] = fmaf(x, k0.w, acc[j][3]);
            acc[j][4] = fmaf(x, k1.x, acc[j][4]); acc[j][5] = fmaf(x, k1.y, acc[j][5]);
            acc[j][6] = fmaf(x, k1.z, acc[j][6]); acc[j][7] = fmaf(x, k1.w, acc[j][7]);
            acc[j][8] = fmaf(x, k2.x, acc[j][8]); acc[j][9] = fmaf(x, k2.y, acc[j][9]);
        }
    }

    #pragma unroll
    for (int j = 0; j < 6; j++) {
        int t = tid + j * 256;
        if (t < T_) {
            __half tmp[16];
            #pragma unroll
            for (int c = 0; c < 16; c++)
                tmp[c] = __float2half_rn((c < C_) ? acc[j][c] : 0.f);
            size_t base = ((size_t)(b * H_ + h) * T_ + t) * 16;
            *(uint4*)(g_convh + base)     = *(uint4*)&tmp[0];
            *(uint4*)(g_convh + base + 8) = *(uint4*)&tmp[8];
        }
    }
}

// ======================= fused HMMA energy kernel =======================
// grid (12, H, B), 256 threads (8 warps), 2 CTAs/SM. CTA: 128t x 512a.
// K = 528: 8 chunks of 64 (enc) + 1 chunk of 16 (conv). Single-pass fp16.
// Double-buffered cp.async staging overlapped with mma.

#define TSTRIDE_B 144                 // bytes per smem row (72 halves)
#define TILE_B  (128 * TSTRIDE_B)     // 18432 bytes per tile
#define BUF_B   (2 * TILE_B)          // A, B = 36864
#define SM_BIAS (2 * BUF_B)           // 73728
#define SM_VV   (SM_BIAS + 2048)
#define SM_SE   (SM_VV + 2048)
#define SMEM_E  (SM_SE + 512)         // 78336

__global__ __launch_bounds__(256, 2) void energy_mma_kernel(
    const float* __restrict__ b_enc, const float* __restrict__ v)
{
    extern __shared__ char dynsmem[];
    float* s_bias = (float*)(dynsmem + SM_BIAS);
    float* s_vv   = (float*)(dynsmem + SM_VV);
    float* s_e    = (float*)(dynsmem + SM_SE);

    int tile = blockIdx.x, h = blockIdx.y, b = blockIdx.z;
    int t0 = tile * 128;
    int tid = threadIdx.x;
    int wid = tid >> 5, lane = tid & 31;
    int wt = wid & 3, wa = wid >> 2;          // warp grid 4(t) x 2(a)

    unsigned sb = smem_u32(dynsmem);

    for (int i = tid; i < A_; i += 256) {
        s_bias[i] = b_enc[h * A_ + i] + g_dec_a[(b * H_ + h) * A_ + i];
        s_vv[i]   = v[h * A_ + i];
    }
    if (tid < 128) s_e[tid] = 0.f;

    auto stage = [&](int g) {
        int at = g / 9, c = g % 9;
        unsigned base = sb + (unsigned)(g & 1) * BUF_B;
        if (c < 8) {
            for (int s = tid; s < 1024; s += 256) {
                int r = s >> 3, seg = s & 7;
                int t = t0 + r;
                int tc = t < T_ ? t : T_ - 1;
                const __half* src = g_enc_h + ((size_t)(b * T_ + tc) * E_ + c * 64 + seg * 8);
                cp16(base + r * TSTRIDE_B + seg * 16, src, (t < T_) ? 16 : 0);
            }
            for (int s = tid; s < 1024; s += 256) {
                int r = s >> 3, seg = s & 7;
                const __half* src = g_wall
                    + ((size_t)(h * A_ + at * 128 + r) * KTOT + c * 64 + seg * 8);
                cp16(base + TILE_B + r * TSTRIDE_B + seg * 16, src, 16);
            }
        } else {
            for (int s = tid; s < 256; s += 256) {
                int r = s >> 1, seg = s & 1;
                int t = t0 + r;
                int tc = t < T_ ? t : T_ - 1;
                const __half* src = g_convh + ((size_t)((b * H_ + h) * T_ + tc) * 16 + seg * 8);
                cp16(base + r * TSTRIDE_B + seg * 16, src, (t < T_) ? 16 : 0);
            }
            for (int s = tid; s < 256; s += 256) {
                int r = s >> 1, seg = s & 1;
                const __half* src = g_wall
                    + ((size_t)(h * A_ + at * 128 + r) * KTOT + 512 + seg * 8);
                cp16(base + TILE_B + r * TSTRIDE_B + seg * 16, src, 16);
            }
        }
        cp_commit();
    };

    unsigned aoff0 = (unsigned)((wt * 32 + 0  + (lane & 15)) * TSTRIDE_B + ((lane >> 4) << 4));
    unsigned aoff1 = (unsigned)((wt * 32 + 16 + (lane & 15)) * TSTRIDE_B + ((lane >> 4) << 4));
    unsigned brow = (unsigned)((lane & 7) + ((lane >> 4) << 3));
    unsigned bcol = (unsigned)(((lane >> 3) & 1) << 4);

    float acc[2][8][4];

    stage(0);
    __syncthreads();

    for (int g = 0; g < 36; g++) {
        int at = g / 9, c = g % 9;
        if (g + 1 < 36) stage(g + 1);
        if (g + 1 < 36) cp_wait1(); else cp_wait0();
        __syncthreads();

        if (c == 0) {
            #pragma unroll
            for (int mi = 0; mi < 2; mi++)
                #pragma unroll
                for (int nn = 0; nn < 8; nn++)
                    #pragma unroll
                    for (int q = 0; q < 4; q++) acc[mi][nn][q] = 0.f;
        }

        unsigned base = sb + (unsigned)(g & 1) * BUF_B;
        unsigned sA = base, sB = base + TILE_B;
        int nks = (c < 8) ? 4 : 1;

        #pragma unroll 1
        for (int ks = 0; ks < nks; ks++) {
            unsigned kb = (unsigned)(ks << 5);
            unsigned aa[2][4], bb[4][4];
            ldsm4(aa[0], sA + aoff0 + kb);
            ldsm4(aa[1], sA + aoff1 + kb);
            #pragma unroll
            for (int np = 0; np < 4; np++) {
                unsigned off = (unsigned)((wa * 64 + np * 16 + brow) * TSTRIDE_B) + bcol + kb;
                ldsm4(bb[np], sB + off);
            }
            #pragma unroll
            for (int mi = 0; mi < 2; mi++)
                #pragma unroll
                for (int np = 0; np < 4; np++)
                    #pragma unroll
                    for (int sub = 0; sub < 2; sub++)
                        mma16816(acc[mi][np * 2 + sub], aa[mi], bb[np][sub * 2], bb[np][sub * 2 + 1]);
        }

        if (c == 8) {
            #pragma unroll
            for (int mi = 0; mi < 2; mi++) {
                float e0 = 0.f, e1 = 0.f;
                #pragma unroll
                for (int nn = 0; nn < 8; nn++) {
                    int ng = at * 128 + wa * 64 + nn * 8 + (lane & 3) * 2;
                    float b0v = s_bias[ng], b1v = s_bias[ng + 1];
                    float v0  = s_vv[ng],  v1  = s_vv[ng + 1];
                    e0 = fmaf(ftanh(acc[mi][nn][0] + b0v), v0, e0);
                    e0 = fmaf(ftanh(acc[mi][nn][1] + b1v), v1, e0);
                    e1 = fmaf(ftanh(acc[mi][nn][2] + b0v), v0, e1);
                    e1 = fmaf(ftanh(acc[mi][nn][3] + b1v), v1, e1);
                }
                e0 += __shfl_xor_sync(0xFFFFFFFF, e0, 1);
                e0 += __shfl_xor_sync(0xFFFFFFFF, e0, 2);
                e1 += __shfl_xor_sync(0xFFFFFFFF, e1, 1);
                e1 += __shfl_xor_sync(0xFFFFFFFF, e1, 2);
                if ((lane & 3) == 0) {
                    int r = wt * 32 + mi * 16 + (lane >> 2);
                    atomicAdd(&s_e[r], e0);
                    atomicAdd(&s_e[r + 8], e1);
                }
            }
        }
        __syncthreads();
    }

    if (tid < 128) {
        int t = t0 + tid;
        if (t < T_) g_energy[(b * H_ + h) * T_ + t] = s_e[tid];
    }
}

// ---------------- masked softmax over T per (b,h) ----------------
__global__ __launch_bounds__(256) void softmax_kernel(
    const int* __restrict__ x_lens, float* __restrict__ aw_out)
{
    int b = blockIdx.x, h = blockIdx.y, tid = threadIdx.x;
    __shared__ float s_em[T_];
    __shared__ float s_red[256];
    int len = x_lens[b];
    const float* e = g_energy + (size_t)(b * H_ + h) * T_;

    float mx = -3.4e38f;
    for (int t = tid; t < T_; t += 256) {
        float m = (t < len) ? 1.0f : -1024.0f;
        float val = e[t] * m;
        s_em[t] = val;
        mx = fmaxf(mx, val);
    }
    s_red[tid] = mx; __syncthreads();
    for (int s = 128; s > 0; s >>= 1) { if (tid < s) s_red[tid] = fmaxf(s_red[tid], s_red[tid + s]); __syncthreads(); }
    mx = s_red[0];
    __syncthreads();
    float sum = 0.f;
    for (int t = tid; t < T_; t += 256) { float ex = __expf(s_em[t] - mx); s_em[t] = ex; sum += ex; }
    s_red[tid] = sum; __syncthreads();
    for (int s = 128; s > 0; s >>= 1) { if (tid < s) s_red[tid] += s_red[tid + s]; __syncthreads(); }
    float inv = 1.0f / s_red[0];
    for (int t = tid; t < T_; t += 256) {
        float a = s_em[t] * inv;
        g_aw[(size_t)(b * H_ + h) * T_ + t] = a;
        aw_out[(size_t)(b * T_ + t) * H_ + h] = a;
    }
}

// ---------------- ctx partials ----------------
__global__ __launch_bounds__(256) void ctx_partial_kernel(const float* __restrict__ enc)
{
    int chunk = blockIdx.x, b = blockIdx.y, tid = threadIdx.x;
    int t0 = chunk * TCH;
    __shared__ float s_aw[H_][TCH];
    for (int i = tid; i < H_ * TCH; i += 256) {
        int h = i / TCH, tt = i % TCH;
        s_aw[h][tt] = g_aw[(size_t)(b * H_ + h) * T_ + t0 + tt];
    }
    __syncthreads();
    float acc0[H_] = {}, acc1[H_] = {};
    int e0 = tid, e1 = tid + 256;
    const float* ep = enc + (size_t)(b * T_ + t0) * E_;
    #pragma unroll 4
    for (int tt = 0; tt < TCH; tt++) {
        float f0 = ep[(size_t)tt * E_ + e0];
        float f1 = ep[(size_t)tt * E_ + e1];
        #pragma unroll
        for (int h = 0; h < H_; h++) {
            float a = s_aw[h][tt];
            acc0[h] = fmaf(f0, a, acc0[h]);
            acc1[h] = fmaf(f1, a, acc1[h]);
        }
    }
    float* p = g_part + (size_t)((b * NCH + chunk) * H_) * E_;
    #pragma unroll
    for (int h = 0; h < H_; h++) { p[h * E_ + e0] = acc0[h]; p[h * E_ + e1] = acc1[h]; }
}

// ---------------- reduce partials + MHA projection ----------------
__global__ __launch_bounds__(256) void final_kernel(
    const float* __restrict__ w_mha, const float* __restrict__ b_mha, float* __restrict__ out)
{
    int b = blockIdx.x, tid = threadIdx.x;
    __shared__ float s_ctx[H_ * E_];
    for (int i = tid; i < H_ * E_; i += 256) {
        float s = 0.f;
        #pragma unroll
        for (int ch = 0; ch < NCH; ch++)
            s += g_part[(size_t)((b * NCH + ch) * H_) * E_ + i];
        s_ctx[i] = s;
    }
    __syncthreads();
    int ea = tid, eb = tid + 256;
    float acc_a = b_mha[ea], acc_b = b_mha[eb];
    #pragma unroll 8
    for (int he = 0; he < H_ * E_; he++) {
        float c = s_ctx[he];
        const float* w = w_mha + (size_t)he * E_;
        acc_a = fmaf(c, w[ea], acc_a);
        acc_b = fmaf(c, w[eb], acc_b);
    }
    out[b * E_ + ea] = acc_a;
    out[b * E_ + eb] = acc_b;
}

// ---------------- launch ----------------
extern "C" void kernel_launch(void* const* d_in, const int* in_sizes, int n_in,
                              void* d_out, int out_size)
{
    const float* enc     = (const float*)d_in[0];
    const int*   x_lens  = (const int*)  d_in[1];
    const float* dec_out = (const float*)d_in[2];
    const float* aw_step = (const float*)d_in[3];
    const float* w_enc   = (const float*)d_in[4];
    const float* b_enc   = (const float*)d_in[5];
    const float* w_dec   = (const float*)d_in[6];
    const float* w_conv  = (const float*)d_in[7];
    const float* conv_k  = (const float*)d_in[8];
    const float* v       = (const float*)d_in[9];
    const float* w_mha   = (const float*)d_in[10];
    const float* b_mha   = (const float*)d_in[11];

    float* out     = (float*)d_out;
    float* ctx_out = out;              // B*E floats
    float* aw_out  = out + B_ * E_;    // B*T*H floats

    cudaFuncSetAttribute(energy_mma_kernel, cudaFuncAttributeMaxDynamicSharedMemorySize, SMEM_E);

    prep_enc_kernel<<<(B_ * T_ * E_ / 4 + 255) / 256, 256>>>(enc);
    prep_w_kernel<<<(H_ * A_ * KTOT + 255) / 256, 256>>>(w_enc, w_conv);
    dec_proj_kernel<<<dim3(B_, H_), 256>>>(dec_out, w_dec);
    conv_kernel<<<dim3(B_, H_), 256>>>(aw_step, conv_k);
    energy_mma_kernel<<<dim3(NCH, H_, B_), 256, SMEM_E>>>(b_enc, v);
    softmax_kernel<<<dim3(B_, H_), 256>>>(x_lens, aw_out);
    ctx_partial_kernel<<<dim3(NCH, B_), 256>>>(enc);
    final_kernel<<<B_, 256>>>(w_mha, b_mha, ctx_out);
}